// round 6
// baseline (speedup 1.0000x reference)
#include <cuda_runtime.h>
#include <cstdint>

#define BB 512
#define TT 1024
#define NN 64
#define NJOBS (2 * BB)

// Bidirectional split of the CRF forward chain.
//   Forward  job: q_t = diag(exp x_t) * E^T q_{t-1},      t = 1..nf
//   Backward job: r_{k-1} = E * (exp(x_k) ∘ r_k),          k = L-1..nf+1
//   log_norm = C_f + C_b + log(q_nf · r_nf)
// Both are 64x64 fp32 matvec recurrences in linear domain with integer-
// exponent renormalization (exponent of element 0 of the exchanged vector).
// E = exp(trans) is register-resident packed as f32x2; the exchanged vector
// is read back as 16 x ld.shared.v2.u64 feeding fma.rn.f32x2.
//
// Persistent kernel: 148 blocks x 4 warps (<=1 warp per SMSP chip-wide),
// warps pull (batch, dir) jobs from a global atomic counter. A combine
// kernel reduces the per-batch dot product and writes the output.

__device__ float    g_qf[BB][NN];
__device__ float    g_rb[BB][NN];
__device__ float    g_cf[BB];
__device__ float    g_cb[BB];
__device__ float    g_sc[BB];
__device__ unsigned g_ctr;

__global__ void crf_init_kernel() { g_ctr = 0u; }

#define LOAD_CHUNK(dst, base)                                                 \
    do {                                                                      \
        asm volatile("ld.shared.v2.u64 {%0,%1}, [%2];"                        \
                     : "=l"(dst[0]), "=l"(dst[1]) : "r"(base));               \
        asm volatile("ld.shared.v2.u64 {%0,%1}, [%2];"                        \
                     : "=l"(dst[2]), "=l"(dst[3]) : "r"((base) + 16));        \
        asm volatile("ld.shared.v2.u64 {%0,%1}, [%2];"                        \
                     : "=l"(dst[4]), "=l"(dst[5]) : "r"((base) + 32));        \
        asm volatile("ld.shared.v2.u64 {%0,%1}, [%2];"                        \
                     : "=l"(dst[6]), "=l"(dst[7]) : "r"((base) + 48));        \
    } while (0)

#define FMA_CHUNK(g, vv)                                                      \
    do {                                                                      \
        _Pragma("unroll")                                                     \
        for (int k = 0; k < 8; k += 4) {                                      \
            asm("fma.rn.f32x2 %0, %1, %2, %0;" : "+l"(a0) : "l"(Ea[8*(g)+k])   , "l"(vv[k]));   \
            asm("fma.rn.f32x2 %0, %1, %2, %0;" : "+l"(b0) : "l"(Eb[8*(g)+k])   , "l"(vv[k]));   \
            asm("fma.rn.f32x2 %0, %1, %2, %0;" : "+l"(a1) : "l"(Ea[8*(g)+k+1]) , "l"(vv[k+1])); \
            asm("fma.rn.f32x2 %0, %1, %2, %0;" : "+l"(b1) : "l"(Eb[8*(g)+k+1]) , "l"(vv[k+1])); \
            asm("fma.rn.f32x2 %0, %1, %2, %0;" : "+l"(a2) : "l"(Ea[8*(g)+k+2]) , "l"(vv[k+2])); \
            asm("fma.rn.f32x2 %0, %1, %2, %0;" : "+l"(b2) : "l"(Eb[8*(g)+k+2]) , "l"(vv[k+2])); \
            asm("fma.rn.f32x2 %0, %1, %2, %0;" : "+l"(a3) : "l"(Ea[8*(g)+k+3]) , "l"(vv[k+3])); \
            asm("fma.rn.f32x2 %0, %1, %2, %0;" : "+l"(b3) : "l"(Eb[8*(g)+k+3]) , "l"(vv[k+3])); \
        }                                                                     \
    } while (0)

// Matvec core: loads the 64-float vector from sbase (double-buffered shared),
// extracts renorm exponent from element 0, accumulates 8 f32x2 chains.
// Results: gl/gh per column pair; e is written out.
#define MATVEC(sbase)                                                         \
    unsigned long long v0[8], v1[8];                                          \
    LOAD_CHUNK(v0, sbase);                                                    \
    LOAD_CHUNK(v1, (sbase) + 64);                                             \
    unsigned q0bits;                                                          \
    asm("mov.b64 {%0,_}, %1;" : "=r"(q0bits) : "l"(v0[0]));                   \
    const int e = (int)((q0bits >> 23) & 0xff) - 127;                         \
    const float scale = __uint_as_float((unsigned)(127 - e) << 23);           \
    unsigned long long a0 = 0ull, a1 = 0ull, a2 = 0ull, a3 = 0ull;            \
    unsigned long long b0 = 0ull, b1 = 0ull, b2 = 0ull, b3 = 0ull;            \
    FMA_CHUNK(0, v0);                                                         \
    LOAD_CHUNK(v0, (sbase) + 128);                                            \
    FMA_CHUNK(1, v1);                                                         \
    LOAD_CHUNK(v1, (sbase) + 192);                                            \
    FMA_CHUNK(2, v0);                                                         \
    FMA_CHUNK(3, v1);                                                         \
    asm("add.rn.f32x2 %0, %0, %1;" : "+l"(a0) : "l"(a1));                     \
    asm("add.rn.f32x2 %0, %0, %1;" : "+l"(a2) : "l"(a3));                     \
    asm("add.rn.f32x2 %0, %0, %1;" : "+l"(b0) : "l"(b1));                     \
    asm("add.rn.f32x2 %0, %0, %1;" : "+l"(b2) : "l"(b3));                     \
    asm("add.rn.f32x2 %0, %0, %1;" : "+l"(a0) : "l"(a2));                     \
    asm("add.rn.f32x2 %0, %0, %1;" : "+l"(b0) : "l"(b2));                     \
    float gal, gah, gbl, gbh;                                                 \
    asm("mov.b64 {%0,%1}, %2;" : "=f"(gal), "=f"(gah) : "l"(a0));             \
    asm("mov.b64 {%0,%1}, %2;" : "=f"(gbl), "=f"(gbh) : "l"(b0));

__global__ __launch_bounds__(128, 1) void crf_half_kernel(
    const float* __restrict__ inputs,   // [B, T, N]
    const float* __restrict__ trans,    // [N, N]
    const int*   __restrict__ tags,     // [B, T]
    const int*   __restrict__ lens)     // [B]
{
    const int lane = threadIdx.x & 31;
    const int wid  = threadIdx.x >> 5;

    __shared__ __align__(16) float pbuf[4][2][NN];

    for (;;) {
        unsigned j;
        if (lane == 0) j = atomicAdd(&g_ctr, 1u);
        j = __shfl_sync(0xffffffffu, j, 0);
        if (j >= NJOBS) return;

        const int b   = (int)(j >> 1);
        const int dir = (int)(j & 1);
        const int L   = lens[b];
        const int nf  = (L - 1) >> 1;          // forward steps
        const size_t tbase = (size_t)b * TT;
        const float* xp = inputs + tbase * NN;

        if (dir == 0) {
            // ================= FORWARD half + sequence scores =============
            // E packed over ROW pairs for owned columns lane / lane+32.
            unsigned long long Ea[NN / 2], Eb[NN / 2];
#pragma unroll
            for (int k = 0; k < NN / 2; ++k) {
                float e0 = __expf(trans[(2 * k)     * NN + lane]);
                float e1 = __expf(trans[(2 * k + 1) * NN + lane]);
                asm("mov.b64 %0, {%1,%2};" : "=l"(Ea[k]) : "f"(e0), "f"(e1));
                float f0 = __expf(trans[(2 * k)     * NN + lane + 32]);
                float f1 = __expf(trans[(2 * k + 1) * NN + lane + 32]);
                asm("mov.b64 %0, {%1,%2};" : "=l"(Eb[k]) : "f"(f0), "f"(f1));
            }

            // sequence scores (unary + binary)
            float sc = 0.f;
            for (int t = lane; t < L; t += 32) {
                int tg = tags[tbase + t];
                sc += inputs[(tbase + t) * NN + tg];
                if (t >= 1) {
                    int tp = tags[tbase + t - 1];
                    sc += trans[tp * NN + tg];
                }
            }
#pragma unroll
            for (int o = 16; o; o >>= 1)
                sc += __shfl_xor_sync(0xffffffffu, sc, o);

            // init q(0) = exp(x0 - M0)
            float x0a = xp[lane];
            float x0b = xp[lane + 32];
            float M0  = __shfl_sync(0xffffffffu, x0a, 0);
            float qa  = __expf(x0a - M0);
            float qb  = __expf(x0b - M0);
            pbuf[wid][0][lane]      = qa;
            pbuf[wid][0][lane + 32] = qb;
            __syncwarp();

            int Ce = 0;
            float xa1 = 0.f, xb1 = 0.f, xa2 = 0.f, xb2 = 0.f;
            if (nf >= 1) { xa1 = xp[NN + lane];     xb1 = xp[NN + lane + 32]; }
            if (nf >= 2) { xa2 = xp[2 * NN + lane]; xb2 = xp[2 * NN + lane + 32]; }

            for (int t = 1; t <= nf; ++t) {
                const unsigned s0 = (unsigned)__cvta_generic_to_shared(
                    &pbuf[wid][(t - 1) & 1][0]);

                const float sxa = __expf(xa1);
                const float sxb = __expf(xb1);
                xa1 = xa2; xb1 = xb2;
                if (t + 2 <= nf) {
                    xa2 = xp[(size_t)(t + 2) * NN + lane];
                    xb2 = xp[(size_t)(t + 2) * NN + lane + 32];
                }

                MATVEC(s0);
                Ce += e;
                qa = (gal + gah) * (sxa * scale);
                qb = (gbl + gbh) * (sxb * scale);

                float* pw = pbuf[wid][t & 1];
                pw[lane]      = qa;
                pw[lane + 32] = qb;
                __syncwarp();
            }

            g_qf[b][lane]      = qa;
            g_qf[b][lane + 32] = qb;
            if (lane == 0) {
                g_cf[b] = M0 + (float)Ce * 0.6931471805599453f;
                g_sc[b] = sc;
            }
        } else {
            // ================= BACKWARD half ==============================
            // r_{L-1} = 1;  r_{k-1} = E * (exp(x_k) ∘ r_k), k = L-1..nf+1.
            // E packed over COLUMN pairs for owned rows lane / lane+32
            // (contiguous in trans).
            unsigned long long Ea[NN / 2], Eb[NN / 2];
#pragma unroll
            for (int k = 0; k < NN / 2; ++k) {
                float e0 = __expf(trans[lane * NN + 2 * k]);
                float e1 = __expf(trans[lane * NN + 2 * k + 1]);
                asm("mov.b64 %0, {%1,%2};" : "=l"(Ea[k]) : "f"(e0), "f"(e1));
                float f0 = __expf(trans[(lane + 32) * NN + 2 * k]);
                float f1 = __expf(trans[(lane + 32) * NN + 2 * k + 1]);
                asm("mov.b64 %0, {%1,%2};" : "=l"(Eb[k]) : "f"(f0), "f"(f1));
            }

            const int nb = (L - 1) - nf;      // backward steps
            float ra = 1.f, rb = 1.f;
            int Ce = 0;

            // prefetch x descending from k = L-1
            float xa1 = 0.f, xb1 = 0.f, xa2 = 0.f, xb2 = 0.f;
            if (nb >= 1) {
                xa1 = xp[(size_t)(L - 1) * NN + lane];
                xb1 = xp[(size_t)(L - 1) * NN + lane + 32];
            }
            if (nb >= 2) {
                xa2 = xp[(size_t)(L - 2) * NN + lane];
                xb2 = xp[(size_t)(L - 2) * NN + lane + 32];
            }

            for (int s = 0; s < nb; ++s) {
                // u = exp(x_k) ∘ r
                const float ua = __expf(xa1) * ra;
                const float ub = __expf(xb1) * rb;
                xa1 = xa2; xb1 = xb2;
                if (s + 2 < nb) {
                    const size_t k2 = (size_t)(L - 1 - (s + 2));
                    xa2 = xp[k2 * NN + lane];
                    xb2 = xp[k2 * NN + lane + 32];
                }

                float* pw = pbuf[wid][s & 1];
                pw[lane]      = ua;
                pw[lane + 32] = ub;
                __syncwarp();

                const unsigned s0 = (unsigned)__cvta_generic_to_shared(
                    &pbuf[wid][s & 1][0]);
                MATVEC(s0);
                Ce += e;
                ra = (gal + gah) * scale;
                rb = (gbl + gbh) * scale;
            }

            g_rb[b][lane]      = ra;
            g_rb[b][lane + 32] = rb;
            if (lane == 0)
                g_cb[b] = (float)Ce * 0.6931471805599453f;
        }
    }
}

__global__ __launch_bounds__(32) void crf_combine_kernel(float* __restrict__ out)
{
    const int b    = blockIdx.x;
    const int lane = threadIdx.x;

    float d = g_qf[b][lane]      * g_rb[b][lane]
            + g_qf[b][lane + 32] * g_rb[b][lane + 32];
#pragma unroll
    for (int o = 16; o; o >>= 1) d += __shfl_xor_sync(0xffffffffu, d, o);

    if (lane == 0) {
        const float log_norm = g_cf[b] + g_cb[b] + __logf(d);
        out[b] = g_sc[b] - log_norm;
    }
}

extern "C" void kernel_launch(void* const* d_in, const int* in_sizes, int n_in,
                              void* d_out, int out_size)
{
    const float* inputs = (const float*)d_in[0];
    const float* trans  = (const float*)d_in[1];
    const int*   tags   = (const int*)d_in[2];
    const int*   lens   = (const int*)d_in[3];
    float*       out    = (float*)d_out;

    crf_init_kernel<<<1, 1>>>();
    crf_half_kernel<<<148, 128>>>(inputs, trans, tags, lens);
    crf_combine_kernel<<<BB, 32>>>(out);
}

// round 7
// speedup vs baseline: 1.3710x; 1.3710x over previous
#include <cuda_runtime.h>
#include <cstdint>

#define BB 512
#define TT 1024
#define NN 64
#define NJOBS (2 * BB)

// Bidirectional split of the CRF forward chain + LPT scheduling.
//   Forward  job: q_t = diag(exp x_t) * E^T q_{t-1},  t = 1..nf
//   Backward job: r_{k-1} = E * (exp(x_k) ∘ r_k),      k = L-1..nf+1
//   log_norm = C_f + C_b + log(q_nf · r_nf)
// Jobs are sorted by length (descending) in an init kernel (bitonic, one
// 1024-thread block); the persistent main kernel (148 blocks x 4 warps,
// <=1 warp per SMSP chip-wide) pulls jobs longest-first from an atomic
// counter -> LPT makespan ~ max half-length (~512 steps) instead of the
// unordered-queue ~2x half-length of R6.

__device__ float          g_qf[BB][NN];
__device__ float          g_rb[BB][NN];
__device__ float          g_cf[BB];
__device__ float          g_cb[BB];
__device__ float          g_sc[BB];
__device__ unsigned       g_ctr;
__device__ unsigned short g_order[NJOBS];

// ---- init: reset counter, sort job ids by length descending ----
__global__ __launch_bounds__(NJOBS) void crf_init_kernel(
    const int* __restrict__ lens)
{
    __shared__ unsigned keys[NJOBS];
    const int tid = threadIdx.x;
    if (tid == 0) g_ctr = 0u;

    const int b   = tid >> 1;
    const int dir = tid & 1;
    const int L   = lens[b];
    const int nf  = (L - 1) >> 1;
    const int len = dir ? (L - 1 - nf) : nf;
    // ascending sort on (512 - len) == descending on len
    keys[tid] = ((unsigned)(512 - len) << 11) | (unsigned)tid;
    __syncthreads();

    for (unsigned k = 2; k <= NJOBS; k <<= 1) {
        for (unsigned j = k >> 1; j > 0; j >>= 1) {
            const unsigned ixj = tid ^ j;
            if (ixj > (unsigned)tid) {
                const unsigned a = keys[tid];
                const unsigned c = keys[ixj];
                const bool asc = ((tid & k) == 0);
                if (asc ? (a > c) : (a < c)) {
                    keys[tid] = c;
                    keys[ixj] = a;
                }
            }
            __syncthreads();
        }
    }
    g_order[tid] = (unsigned short)(keys[tid] & 0x7FFu);
}

#define LOAD_CHUNK(dst, base)                                                 \
    do {                                                                      \
        asm volatile("ld.shared.v2.u64 {%0,%1}, [%2];"                        \
                     : "=l"(dst[0]), "=l"(dst[1]) : "r"(base));               \
        asm volatile("ld.shared.v2.u64 {%0,%1}, [%2];"                        \
                     : "=l"(dst[2]), "=l"(dst[3]) : "r"((base) + 16));        \
        asm volatile("ld.shared.v2.u64 {%0,%1}, [%2];"                        \
                     : "=l"(dst[4]), "=l"(dst[5]) : "r"((base) + 32));        \
        asm volatile("ld.shared.v2.u64 {%0,%1}, [%2];"                        \
                     : "=l"(dst[6]), "=l"(dst[7]) : "r"((base) + 48));        \
    } while (0)

#define FMA_CHUNK(g, vv)                                                      \
    do {                                                                      \
        _Pragma("unroll")                                                     \
        for (int k = 0; k < 8; k += 4) {                                      \
            asm("fma.rn.f32x2 %0, %1, %2, %0;" : "+l"(a0) : "l"(Ea[8*(g)+k])   , "l"(vv[k]));   \
            asm("fma.rn.f32x2 %0, %1, %2, %0;" : "+l"(b0) : "l"(Eb[8*(g)+k])   , "l"(vv[k]));   \
            asm("fma.rn.f32x2 %0, %1, %2, %0;" : "+l"(a1) : "l"(Ea[8*(g)+k+1]) , "l"(vv[k+1])); \
            asm("fma.rn.f32x2 %0, %1, %2, %0;" : "+l"(b1) : "l"(Eb[8*(g)+k+1]) , "l"(vv[k+1])); \
            asm("fma.rn.f32x2 %0, %1, %2, %0;" : "+l"(a2) : "l"(Ea[8*(g)+k+2]) , "l"(vv[k+2])); \
            asm("fma.rn.f32x2 %0, %1, %2, %0;" : "+l"(b2) : "l"(Eb[8*(g)+k+2]) , "l"(vv[k+2])); \
            asm("fma.rn.f32x2 %0, %1, %2, %0;" : "+l"(a3) : "l"(Ea[8*(g)+k+3]) , "l"(vv[k+3])); \
            asm("fma.rn.f32x2 %0, %1, %2, %0;" : "+l"(b3) : "l"(Eb[8*(g)+k+3]) , "l"(vv[k+3])); \
        }                                                                     \
    } while (0)

#define MATVEC(sbase)                                                         \
    unsigned long long v0[8], v1[8];                                          \
    LOAD_CHUNK(v0, sbase);                                                    \
    LOAD_CHUNK(v1, (sbase) + 64);                                             \
    unsigned q0bits;                                                          \
    asm("mov.b64 {%0,_}, %1;" : "=r"(q0bits) : "l"(v0[0]));                   \
    const int e = (int)((q0bits >> 23) & 0xff) - 127;                         \
    const float scale = __uint_as_float((unsigned)(127 - e) << 23);           \
    unsigned long long a0 = 0ull, a1 = 0ull, a2 = 0ull, a3 = 0ull;            \
    unsigned long long b0 = 0ull, b1 = 0ull, b2 = 0ull, b3 = 0ull;            \
    FMA_CHUNK(0, v0);                                                         \
    LOAD_CHUNK(v0, (sbase) + 128);                                            \
    FMA_CHUNK(1, v1);                                                         \
    LOAD_CHUNK(v1, (sbase) + 192);                                            \
    FMA_CHUNK(2, v0);                                                         \
    FMA_CHUNK(3, v1);                                                         \
    asm("add.rn.f32x2 %0, %0, %1;" : "+l"(a0) : "l"(a1));                     \
    asm("add.rn.f32x2 %0, %0, %1;" : "+l"(a2) : "l"(a3));                     \
    asm("add.rn.f32x2 %0, %0, %1;" : "+l"(b0) : "l"(b1));                     \
    asm("add.rn.f32x2 %0, %0, %1;" : "+l"(b2) : "l"(b3));                     \
    asm("add.rn.f32x2 %0, %0, %1;" : "+l"(a0) : "l"(a2));                     \
    asm("add.rn.f32x2 %0, %0, %1;" : "+l"(b0) : "l"(b2));                     \
    float gal, gah, gbl, gbh;                                                 \
    asm("mov.b64 {%0,%1}, %2;" : "=f"(gal), "=f"(gah) : "l"(a0));             \
    asm("mov.b64 {%0,%1}, %2;" : "=f"(gbl), "=f"(gbh) : "l"(b0));

__global__ __launch_bounds__(128, 1) void crf_half_kernel(
    const float* __restrict__ inputs,   // [B, T, N]
    const float* __restrict__ trans,    // [N, N]
    const int*   __restrict__ tags,     // [B, T]
    const int*   __restrict__ lens)     // [B]
{
    const int lane = threadIdx.x & 31;
    const int wid  = threadIdx.x >> 5;

    __shared__ __align__(16) float pbuf[4][2][NN];

    for (;;) {
        unsigned j;
        if (lane == 0) j = atomicAdd(&g_ctr, 1u);
        j = __shfl_sync(0xffffffffu, j, 0);
        if (j >= NJOBS) return;
        j = g_order[j];                      // LPT order

        const int b   = (int)(j >> 1);
        const int dir = (int)(j & 1);
        const int L   = lens[b];
        const int nf  = (L - 1) >> 1;
        const size_t tbase = (size_t)b * TT;
        const float* xp = inputs + tbase * NN;

        if (dir == 0) {
            // ---------------- FORWARD half + sequence scores -------------
            unsigned long long Ea[NN / 2], Eb[NN / 2];
#pragma unroll
            for (int k = 0; k < NN / 2; ++k) {
                float e0 = __expf(trans[(2 * k)     * NN + lane]);
                float e1 = __expf(trans[(2 * k + 1) * NN + lane]);
                asm("mov.b64 %0, {%1,%2};" : "=l"(Ea[k]) : "f"(e0), "f"(e1));
                float f0 = __expf(trans[(2 * k)     * NN + lane + 32]);
                float f1 = __expf(trans[(2 * k + 1) * NN + lane + 32]);
                asm("mov.b64 %0, {%1,%2};" : "=l"(Eb[k]) : "f"(f0), "f"(f1));
            }

            float sc = 0.f;
            for (int t = lane; t < L; t += 32) {
                int tg = tags[tbase + t];
                sc += inputs[(tbase + t) * NN + tg];
                if (t >= 1) {
                    int tp = tags[tbase + t - 1];
                    sc += trans[tp * NN + tg];
                }
            }
#pragma unroll
            for (int o = 16; o; o >>= 1)
                sc += __shfl_xor_sync(0xffffffffu, sc, o);

            float x0a = xp[lane];
            float x0b = xp[lane + 32];
            float M0  = __shfl_sync(0xffffffffu, x0a, 0);
            float qa  = __expf(x0a - M0);
            float qb  = __expf(x0b - M0);
            pbuf[wid][0][lane]      = qa;
            pbuf[wid][0][lane + 32] = qb;
            __syncwarp();

            int Ce = 0;
            float xa1 = 0.f, xb1 = 0.f, xa2 = 0.f, xb2 = 0.f;
            if (nf >= 1) { xa1 = xp[NN + lane];     xb1 = xp[NN + lane + 32]; }
            if (nf >= 2) { xa2 = xp[2 * NN + lane]; xb2 = xp[2 * NN + lane + 32]; }

            for (int t = 1; t <= nf; ++t) {
                const unsigned s0 = (unsigned)__cvta_generic_to_shared(
                    &pbuf[wid][(t - 1) & 1][0]);

                const float sxa = __expf(xa1);
                const float sxb = __expf(xb1);
                xa1 = xa2; xb1 = xb2;
                if (t + 2 <= nf) {
                    xa2 = xp[(size_t)(t + 2) * NN + lane];
                    xb2 = xp[(size_t)(t + 2) * NN + lane + 32];
                }

                MATVEC(s0);
                Ce += e;
                qa = (gal + gah) * (sxa * scale);
                qb = (gbl + gbh) * (sxb * scale);

                float* pw = pbuf[wid][t & 1];
                pw[lane]      = qa;
                pw[lane + 32] = qb;
                __syncwarp();
            }

            g_qf[b][lane]      = qa;
            g_qf[b][lane + 32] = qb;
            if (lane == 0) {
                g_cf[b] = M0 + (float)Ce * 0.6931471805599453f;
                g_sc[b] = sc;
            }
        } else {
            // ---------------- BACKWARD half ------------------------------
            unsigned long long Ea[NN / 2], Eb[NN / 2];
#pragma unroll
            for (int k = 0; k < NN / 2; ++k) {
                float e0 = __expf(trans[lane * NN + 2 * k]);
                float e1 = __expf(trans[lane * NN + 2 * k + 1]);
                asm("mov.b64 %0, {%1,%2};" : "=l"(Ea[k]) : "f"(e0), "f"(e1));
                float f0 = __expf(trans[(lane + 32) * NN + 2 * k]);
                float f1 = __expf(trans[(lane + 32) * NN + 2 * k + 1]);
                asm("mov.b64 %0, {%1,%2};" : "=l"(Eb[k]) : "f"(f0), "f"(f1));
            }

            const int nb = (L - 1) - nf;
            float ra = 1.f, rb = 1.f;
            int Ce = 0;

            float xa1 = 0.f, xb1 = 0.f, xa2 = 0.f, xb2 = 0.f;
            if (nb >= 1) {
                xa1 = xp[(size_t)(L - 1) * NN + lane];
                xb1 = xp[(size_t)(L - 1) * NN + lane + 32];
            }
            if (nb >= 2) {
                xa2 = xp[(size_t)(L - 2) * NN + lane];
                xb2 = xp[(size_t)(L - 2) * NN + lane + 32];
            }

            for (int s = 0; s < nb; ++s) {
                const float ua = __expf(xa1) * ra;
                const float ub = __expf(xb1) * rb;
                xa1 = xa2; xb1 = xb2;
                if (s + 2 < nb) {
                    const size_t k2 = (size_t)(L - 1 - (s + 2));
                    xa2 = xp[k2 * NN + lane];
                    xb2 = xp[k2 * NN + lane + 32];
                }

                float* pw = pbuf[wid][s & 1];
                pw[lane]      = ua;
                pw[lane + 32] = ub;
                __syncwarp();

                const unsigned s0 = (unsigned)__cvta_generic_to_shared(
                    &pbuf[wid][s & 1][0]);
                MATVEC(s0);
                Ce += e;
                ra = (gal + gah) * scale;
                rb = (gbl + gbh) * scale;
            }

            g_rb[b][lane]      = ra;
            g_rb[b][lane + 32] = rb;
            if (lane == 0)
                g_cb[b] = (float)Ce * 0.6931471805599453f;
        }
    }
}

__global__ __launch_bounds__(32) void crf_combine_kernel(float* __restrict__ out)
{
    const int b    = blockIdx.x;
    const int lane = threadIdx.x;

    float d = g_qf[b][lane]      * g_rb[b][lane]
            + g_qf[b][lane + 32] * g_rb[b][lane + 32];
#pragma unroll
    for (int o = 16; o; o >>= 1) d += __shfl_xor_sync(0xffffffffu, d, o);

    if (lane == 0) {
        const float log_norm = g_cf[b] + g_cb[b] + __logf(d);
        out[b] = g_sc[b] - log_norm;
    }
}

extern "C" void kernel_launch(void* const* d_in, const int* in_sizes, int n_in,
                              void* d_out, int out_size)
{
    const float* inputs = (const float*)d_in[0];
    const float* trans  = (const float*)d_in[1];
    const int*   tags   = (const int*)d_in[2];
    const int*   lens   = (const int*)d_in[3];
    float*       out    = (float*)d_out;

    crf_init_kernel<<<1, NJOBS>>>(lens);
    crf_half_kernel<<<148, 128>>>(inputs, trans, tags, lens);
    crf_combine_kernel<<<BB, 32>>>(out);
}

// round 8
// speedup vs baseline: 1.4451x; 1.0541x over previous
#include <cuda_runtime.h>
#include <cstdint>

#define BB 512
#define TT 1024
#define NN 64
#define NJOBS (2 * BB)

// Bidirectional split of the CRF forward chain + LPT scheduling + fused
// combine.
//   Forward  job: q_t = diag(exp x_t) * E^T q_{t-1},  t = 1..nf
//   Backward job: r_{k-1} = E * (exp(x_k) ∘ r_k),      k = L-1..nf+1
//   log_norm = C_f + C_b + log(q_nf · r_nf)
// Jobs ordered longest-first by a histogram-rank init kernel (lengths are
// in [0,512]); the persistent main kernel (148 blocks x 4 warps, <=1 warp
// per SMSP chip-wide) pulls jobs from an atomic counter. The second half
// to finish for a batch performs the combine in-place (per-batch done
// counter), eliminating the separate combine launch. Per-step __syncwarp
// is elided: the warp is non-divergent and all smem ops are asm volatile,
// so per-warp in-order MIO guarantees STS->LDS ordering.

__device__ float          g_qf[BB][NN];
__device__ float          g_rb[BB][NN];
__device__ float          g_cf[BB];
__device__ float          g_cb[BB];
__device__ float          g_sc[BB];
__device__ unsigned       g_ctr;
__device__ unsigned       g_done[BB];
__device__ unsigned short g_order[NJOBS];

// ---- init: reset counters, rank jobs by length descending --------------
__global__ __launch_bounds__(NJOBS) void crf_init_kernel(
    const int* __restrict__ lens)
{
    __shared__ unsigned hist[513];
    __shared__ unsigned ofs[513];
    __shared__ unsigned scan[NJOBS];
    const int tid = threadIdx.x;

    if (tid == 0) g_ctr = 0u;
    if (tid < BB) g_done[tid] = 0u;
    if (tid < 513) { hist[tid] = 0u; ofs[tid] = 0u; }
    __syncthreads();

    const int b   = tid >> 1;
    const int dir = tid & 1;
    const int L   = lens[b];
    const int nf  = (L - 1) >> 1;
    const int len = dir ? (L - 1 - nf) : nf;   // 0..512
    atomicAdd(&hist[len], 1u);
    __syncthreads();

    // inclusive scan over descending-length bins: scan[k] = sum hist[512-k']
    scan[tid] = (tid <= 512) ? hist[512 - tid] : 0u;
    __syncthreads();
#pragma unroll
    for (int off = 1; off < NJOBS; off <<= 1) {
        unsigned v = (tid >= off) ? scan[tid - off] : 0u;
        __syncthreads();
        scan[tid] += v;
        __syncthreads();
    }

    const unsigned k     = (unsigned)(512 - len);
    const unsigned start = k ? scan[k - 1] : 0u;   // # jobs strictly longer
    const unsigned pos   = start + atomicAdd(&ofs[len], 1u);
    g_order[pos] = (unsigned short)tid;
}

#define LOAD_CHUNK(dst, base)                                                 \
    do {                                                                      \
        asm volatile("ld.shared.v2.u64 {%0,%1}, [%2];"                        \
                     : "=l"(dst[0]), "=l"(dst[1]) : "r"(base));               \
        asm volatile("ld.shared.v2.u64 {%0,%1}, [%2];"                        \
                     : "=l"(dst[2]), "=l"(dst[3]) : "r"((base) + 16));        \
        asm volatile("ld.shared.v2.u64 {%0,%1}, [%2];"                        \
                     : "=l"(dst[4]), "=l"(dst[5]) : "r"((base) + 32));        \
        asm volatile("ld.shared.v2.u64 {%0,%1}, [%2];"                        \
                     : "=l"(dst[6]), "=l"(dst[7]) : "r"((base) + 48));        \
    } while (0)

#define FMA_CHUNK(g, vv)                                                      \
    do {                                                                      \
        _Pragma("unroll")                                                     \
        for (int k = 0; k < 8; k += 4) {                                      \
            asm("fma.rn.f32x2 %0, %1, %2, %0;" : "+l"(a0) : "l"(Ea[8*(g)+k])   , "l"(vv[k]));   \
            asm("fma.rn.f32x2 %0, %1, %2, %0;" : "+l"(b0) : "l"(Eb[8*(g)+k])   , "l"(vv[k]));   \
            asm("fma.rn.f32x2 %0, %1, %2, %0;" : "+l"(a1) : "l"(Ea[8*(g)+k+1]) , "l"(vv[k+1])); \
            asm("fma.rn.f32x2 %0, %1, %2, %0;" : "+l"(b1) : "l"(Eb[8*(g)+k+1]) , "l"(vv[k+1])); \
            asm("fma.rn.f32x2 %0, %1, %2, %0;" : "+l"(a2) : "l"(Ea[8*(g)+k+2]) , "l"(vv[k+2])); \
            asm("fma.rn.f32x2 %0, %1, %2, %0;" : "+l"(b2) : "l"(Eb[8*(g)+k+2]) , "l"(vv[k+2])); \
            asm("fma.rn.f32x2 %0, %1, %2, %0;" : "+l"(a3) : "l"(Ea[8*(g)+k+3]) , "l"(vv[k+3])); \
            asm("fma.rn.f32x2 %0, %1, %2, %0;" : "+l"(b3) : "l"(Eb[8*(g)+k+3]) , "l"(vv[k+3])); \
        }                                                                     \
    } while (0)

#define MATVEC(sbase)                                                         \
    unsigned long long v0[8], v1[8];                                          \
    LOAD_CHUNK(v0, sbase);                                                    \
    LOAD_CHUNK(v1, (sbase) + 64);                                             \
    unsigned q0bits;                                                          \
    asm("mov.b64 {%0,_}, %1;" : "=r"(q0bits) : "l"(v0[0]));                   \
    const int e = (int)((q0bits >> 23) & 0xff) - 127;                         \
    const float scale = __uint_as_float((unsigned)(127 - e) << 23);           \
    unsigned long long a0 = 0ull, a1 = 0ull, a2 = 0ull, a3 = 0ull;            \
    unsigned long long b0 = 0ull, b1 = 0ull, b2 = 0ull, b3 = 0ull;            \
    FMA_CHUNK(0, v0);                                                         \
    LOAD_CHUNK(v0, (sbase) + 128);                                            \
    FMA_CHUNK(1, v1);                                                         \
    LOAD_CHUNK(v1, (sbase) + 192);                                            \
    FMA_CHUNK(2, v0);                                                         \
    FMA_CHUNK(3, v1);                                                         \
    asm("add.rn.f32x2 %0, %0, %1;" : "+l"(a0) : "l"(a1));                     \
    asm("add.rn.f32x2 %0, %0, %1;" : "+l"(a2) : "l"(a3));                     \
    asm("add.rn.f32x2 %0, %0, %1;" : "+l"(b0) : "l"(b1));                     \
    asm("add.rn.f32x2 %0, %0, %1;" : "+l"(b2) : "l"(b3));                     \
    asm("add.rn.f32x2 %0, %0, %1;" : "+l"(a0) : "l"(a2));                     \
    asm("add.rn.f32x2 %0, %0, %1;" : "+l"(b0) : "l"(b2));                     \
    float gal, gah, gbl, gbh;                                                 \
    asm("mov.b64 {%0,%1}, %2;" : "=f"(gal), "=f"(gah) : "l"(a0));             \
    asm("mov.b64 {%0,%1}, %2;" : "=f"(gbl), "=f"(gbh) : "l"(b0));

#define STS32(addr, val)                                                      \
    asm volatile("st.shared.b32 [%0], %1;" :: "r"(addr), "f"(val) : "memory")

// Combine (second finisher): reads both halves from L2 and writes out[b].
__device__ __forceinline__ void crf_combine(int b, int lane,
                                            float* __restrict__ out)
{
    const float d0 = __ldcg(&g_qf[b][lane])      * __ldcg(&g_rb[b][lane]);
    const float d1 = __ldcg(&g_qf[b][lane + 32]) * __ldcg(&g_rb[b][lane + 32]);
    float d = d0 + d1;
#pragma unroll
    for (int o = 16; o; o >>= 1) d += __shfl_xor_sync(0xffffffffu, d, o);
    if (lane == 0) {
        const float log_norm = __ldcg(&g_cf[b]) + __ldcg(&g_cb[b]) + __logf(d);
        out[b] = __ldcg(&g_sc[b]) - log_norm;
    }
}

__global__ __launch_bounds__(128, 1) void crf_half_kernel(
    const float* __restrict__ inputs,   // [B, T, N]
    const float* __restrict__ trans,    // [N, N]
    const int*   __restrict__ tags,     // [B, T]
    const int*   __restrict__ lens,     // [B]
    float*       __restrict__ out)      // [B]
{
    const int lane = threadIdx.x & 31;
    const int wid  = threadIdx.x >> 5;

    __shared__ __align__(16) float pbuf[4][2][NN];

    for (;;) {
        unsigned j;
        if (lane == 0) j = atomicAdd(&g_ctr, 1u);
        j = __shfl_sync(0xffffffffu, j, 0);
        if (j >= NJOBS) return;
        j = g_order[j];                      // LPT order

        const int b   = (int)(j >> 1);
        const int dir = (int)(j & 1);
        const int L   = lens[b];
        const int nf  = (L - 1) >> 1;
        const size_t tbase = (size_t)b * TT;
        const float* xp = inputs + tbase * NN;

        const unsigned sw0 = (unsigned)__cvta_generic_to_shared(
            &pbuf[wid][0][0]);
        const unsigned sA0 = sw0 + (unsigned)(lane * 4);
        const unsigned sA1 = sw0 + (unsigned)((lane + 32) * 4);
        const unsigned sB0 = sA0 + NN * 4;
        const unsigned sB1 = sA1 + NN * 4;

        if (dir == 0) {
            // ---------------- FORWARD half + sequence scores -------------
            unsigned long long Ea[NN / 2], Eb[NN / 2];
#pragma unroll
            for (int k = 0; k < NN / 2; ++k) {
                float e0 = __expf(trans[(2 * k)     * NN + lane]);
                float e1 = __expf(trans[(2 * k + 1) * NN + lane]);
                asm("mov.b64 %0, {%1,%2};" : "=l"(Ea[k]) : "f"(e0), "f"(e1));
                float f0 = __expf(trans[(2 * k)     * NN + lane + 32]);
                float f1 = __expf(trans[(2 * k + 1) * NN + lane + 32]);
                asm("mov.b64 %0, {%1,%2};" : "=l"(Eb[k]) : "f"(f0), "f"(f1));
            }

            float sc = 0.f;
            for (int t = lane; t < L; t += 32) {
                int tg = tags[tbase + t];
                sc += inputs[(tbase + t) * NN + tg];
                if (t >= 1) {
                    int tp = tags[tbase + t - 1];
                    sc += trans[tp * NN + tg];
                }
            }
#pragma unroll
            for (int o = 16; o; o >>= 1)
                sc += __shfl_xor_sync(0xffffffffu, sc, o);

            float x0a = xp[lane];
            float x0b = xp[lane + 32];
            float M0  = __shfl_sync(0xffffffffu, x0a, 0);
            float qa  = __expf(x0a - M0);
            float qb  = __expf(x0b - M0);
            STS32(sA0, qa);
            STS32(sA1, qb);

            int Ce = 0;
            float xa1 = 0.f, xb1 = 0.f, xa2 = 0.f, xb2 = 0.f;
            if (nf >= 1) { xa1 = xp[NN + lane];     xb1 = xp[NN + lane + 32]; }
            if (nf >= 2) { xa2 = xp[2 * NN + lane]; xb2 = xp[2 * NN + lane + 32]; }

            for (int t = 1; t <= nf; ++t) {
                const unsigned rd = ((t - 1) & 1) ? (sw0 + NN * 4) : sw0;

                const float sxa = __expf(xa1);
                const float sxb = __expf(xb1);
                xa1 = xa2; xb1 = xb2;
                if (t + 2 <= nf) {
                    xa2 = xp[(size_t)(t + 2) * NN + lane];
                    xb2 = xp[(size_t)(t + 2) * NN + lane + 32];
                }

                MATVEC(rd);
                Ce += e;
                qa = (gal + gah) * (sxa * scale);
                qb = (gbl + gbh) * (sxb * scale);

                if (t & 1) { STS32(sB0, qa); STS32(sB1, qb); }
                else       { STS32(sA0, qa); STS32(sA1, qb); }
            }

            g_qf[b][lane]      = qa;
            g_qf[b][lane + 32] = qb;
            if (lane == 0) {
                g_cf[b] = M0 + (float)Ce * 0.6931471805599453f;
                g_sc[b] = sc;
            }
        } else {
            // ---------------- BACKWARD half ------------------------------
            unsigned long long Ea[NN / 2], Eb[NN / 2];
#pragma unroll
            for (int k = 0; k < NN / 2; ++k) {
                float e0 = __expf(trans[lane * NN + 2 * k]);
                float e1 = __expf(trans[lane * NN + 2 * k + 1]);
                asm("mov.b64 %0, {%1,%2};" : "=l"(Ea[k]) : "f"(e0), "f"(e1));
                float f0 = __expf(trans[(lane + 32) * NN + 2 * k]);
                float f1 = __expf(trans[(lane + 32) * NN + 2 * k + 1]);
                asm("mov.b64 %0, {%1,%2};" : "=l"(Eb[k]) : "f"(f0), "f"(f1));
            }

            const int nb = (L - 1) - nf;
            float ra = 1.f, rb = 1.f;
            int Ce = 0;

            float xa1 = 0.f, xb1 = 0.f, xa2 = 0.f, xb2 = 0.f;
            if (nb >= 1) {
                xa1 = xp[(size_t)(L - 1) * NN + lane];
                xb1 = xp[(size_t)(L - 1) * NN + lane + 32];
            }
            if (nb >= 2) {
                xa2 = xp[(size_t)(L - 2) * NN + lane];
                xb2 = xp[(size_t)(L - 2) * NN + lane + 32];
            }

            for (int s = 0; s < nb; ++s) {
                const float ua = __expf(xa1) * ra;
                const float ub = __expf(xb1) * rb;
                xa1 = xa2; xb1 = xb2;
                if (s + 2 < nb) {
                    const size_t k2 = (size_t)(L - 1 - (s + 2));
                    xa2 = xp[k2 * NN + lane];
                    xb2 = xp[k2 * NN + lane + 32];
                }

                unsigned rd;
                if (s & 1) { STS32(sB0, ua); STS32(sB1, ub); rd = sw0 + NN * 4; }
                else       { STS32(sA0, ua); STS32(sA1, ub); rd = sw0; }

                MATVEC(rd);
                Ce += e;
                ra = (gal + gah) * scale;
                rb = (gbl + gbh) * scale;
            }

            g_rb[b][lane]      = ra;
            g_rb[b][lane + 32] = rb;
            if (lane == 0)
                g_cb[b] = (float)Ce * 0.6931471805599453f;
        }

        // ---- completion: second finisher combines ----
        __threadfence();
        unsigned old = 0;
        if (lane == 0) old = atomicAdd(&g_done[b], 1u);
        old = __shfl_sync(0xffffffffu, old, 0);
        if (old == 1u) {
            __threadfence();
            crf_combine(b, lane, out);
        }
    }
}

extern "C" void kernel_launch(void* const* d_in, const int* in_sizes, int n_in,
                              void* d_out, int out_size)
{
    const float* inputs = (const float*)d_in[0];
    const float* trans  = (const float*)d_in[1];
    const int*   tags   = (const int*)d_in[2];
    const int*   lens   = (const int*)d_in[3];
    float*       out    = (float*)d_out;

    crf_init_kernel<<<1, NJOBS>>>(lens);
    crf_half_kernel<<<148, 128>>>(inputs, trans, tags, lens, out);
}